// round 8
// baseline (speedup 1.0000x reference)
#include <cuda_runtime.h>
#include <math.h>
#include <stdint.h>

#define H 1024
#define V 50257
#define L 128

#define OT_TILE 4
#define OT_NTF  (V / OT_TILE)                    // 12564 full tiles (rows 0..50255)
#define OT_GRID 592                              // 148 SMs x 4 resident
#define TILE_BYTES (OT_TILE * H * 4)             // 16384

#define GT_TILES 2048                            // 8192 gate rows / 4

// ---- scratch (no allocations allowed), 16B-aligned ----
__device__ __align__(16) float g_attn_scratch[L];
__device__ __align__(16) float g_attn_applied[H];
__device__ __align__(16) float g_x[H];
__device__ __align__(16) float g_h[H];
__device__ __align__(16) float g_gates[4 * H];
__device__ __align__(16) float g_bmax[OT_GRID];
__device__ __align__(16) float g_bsum[OT_GRID];
__device__ float    g_logZ;
__device__ unsigned g_ctr_attn = 0;
__device__ unsigned g_ctr_out  = 0;

__device__ __forceinline__ float warp_sum(float v) {
    #pragma unroll
    for (int o = 16; o; o >>= 1) v += __shfl_down_sync(0xffffffffu, v, o);
    return v;
}
__device__ __forceinline__ float warp_max(float v) {
    #pragma unroll
    for (int o = 16; o; o >>= 1) v = fmaxf(v, __shfl_down_sync(0xffffffffu, v, o));
    return v;
}
__device__ __forceinline__ float dot4(float4 a, float4 b) {
    return a.x * b.x + a.y * b.y + a.z * b.z + a.w * b.w;
}
__device__ __forceinline__ uint64_t mkpolicy() {
    uint64_t p;
    asm("createpolicy.fractional.L2::evict_first.b64 %0, 1.0;" : "=l"(p));
    return p;
}
// one-instruction 16KB bulk copy (TMA/UBLKCP path, bypasses per-LDG issue cap)
__device__ __forceinline__ void bulk_cp(void* dst_smem, const void* src,
                                        unsigned bytes, unsigned mbar, uint64_t pol) {
    unsigned d = (unsigned)__cvta_generic_to_shared(dst_smem);
    asm volatile(
        "cp.async.bulk.shared::cluster.global.mbarrier::complete_tx::bytes.L2::cache_hint"
        " [%0], [%1], %2, [%3], %4;"
        :: "r"(d), "l"(src), "r"(bytes), "r"(mbar), "l"(pol) : "memory");
}
__device__ __forceinline__ void mbar_init(unsigned mbar, unsigned cnt) {
    asm volatile("mbarrier.init.shared.b64 [%0], %1;" :: "r"(mbar), "r"(cnt) : "memory");
}
__device__ __forceinline__ void mbar_expect(unsigned mbar, unsigned bytes) {
    asm volatile("mbarrier.arrive.expect_tx.shared.b64 _, [%0], %1;"
                 :: "r"(mbar), "r"(bytes) : "memory");
}
__device__ __forceinline__ void mbar_wait(unsigned mbar, unsigned parity) {
    asm volatile(
        "{\n\t.reg .pred P;\n\t"
        "W_%=:\n\t"
        "mbarrier.try_wait.parity.acquire.cta.shared::cta.b64 P, [%0], %1, 0x989680;\n\t"
        "@P bra.uni D_%=;\n\t"
        "bra.uni W_%=;\n\t"
        "D_%=:\n\t}"
        :: "r"(mbar), "r"(parity) : "memory");
}
__device__ __forceinline__ unsigned smem_u32(const void* p) {
    return (unsigned)__cvta_generic_to_shared(p);
}

// ---------------------------------------------------------------------------
// attn logits (block per row) + fused softmax in last arriving block
// ---------------------------------------------------------------------------
__global__ void k_attn(const int* __restrict__ tokens,
                       const float* __restrict__ emb,
                       const float* __restrict__ h0,
                       const float* __restrict__ attn_W,
                       const float* __restrict__ attn_b,
                       float* __restrict__ attn_w_out) {
    int l = blockIdx.x;
    const float4* erow = (const float4*)(emb + (long)tokens[0] * H);
    const float4* hrow = (const float4*)h0;
    const float4* w    = (const float4*)(attn_W + (long)l * 2 * H);
    float acc = 0.f;
    for (int i = threadIdx.x; i < 2 * H / 4; i += blockDim.x) {
        float4 wv = __ldcs(w + i);
        float4 xv = (i < H / 4) ? erow[i] : hrow[i - H / 4];
        acc += dot4(wv, xv);
    }
    __shared__ float s[8];
    acc = warp_sum(acc);
    if ((threadIdx.x & 31) == 0) s[threadIdx.x >> 5] = acc;
    __syncthreads();
    __shared__ unsigned is_last;
    if (threadIdx.x == 0) {
        float v = 0.f;
        #pragma unroll
        for (int k = 0; k < 8; k++) v += s[k];
        g_attn_scratch[l] = v + attn_b[l];
        __threadfence();
        is_last = (atomicAdd(&g_ctr_attn, 1u) == L - 1);
    }
    __syncthreads();
    if (!is_last) return;

    __threadfence();
    __shared__ float sm[L];
    int t = threadIdx.x;
    float v = 0.f;
    if (t < L) { v = g_attn_scratch[t]; sm[t] = v; }
    __syncthreads();
    if (t < L) {
        for (int st = 64; st; st >>= 1) { if (t < st) sm[t] = fmaxf(sm[t], sm[t + st]); __syncthreads(); }
    } else { for (int st = 64; st; st >>= 1) __syncthreads(); }
    float m = sm[0]; __syncthreads();
    float e = (t < L) ? expf(v - m) : 0.f;
    if (t < L) sm[t] = e;
    __syncthreads();
    if (t < L) {
        for (int st = 64; st; st >>= 1) { if (t < st) sm[t] += sm[t + st]; __syncthreads(); }
    } else { for (int st = 64; st; st >>= 1) __syncthreads(); }
    if (t < L) {
        float wgt = e / sm[0];
        attn_w_out[t]     = wgt;
        g_attn_scratch[t] = wgt;
    }
    if (t == 0) g_ctr_attn = 0;
}

// ---------------------------------------------------------------------------
// attn_applied[j] = sum_l w[l] * enc[l][j]
// ---------------------------------------------------------------------------
__global__ void k_attn_applied(const float* __restrict__ enc) {
    int t  = threadIdx.x;
    int jl = t & 31, lg = t >> 5;
    int j  = blockIdx.x * 32 + jl;
    float acc = 0.f;
    #pragma unroll
    for (int k = 0; k < 16; k++) {
        int l = lg * 16 + k;
        acc += g_attn_scratch[l] * enc[l * H + j];
    }
    __shared__ float s[8][32];
    s[lg][jl] = acc;
    __syncthreads();
    if (lg == 0) {
        float v = acc;
        #pragma unroll
        for (int k = 1; k < 8; k++) v += s[k][jl];
        g_attn_applied[j] = v;
    }
}

// ---------------------------------------------------------------------------
// x = relu(comb_W @ [embedded||attn_applied] + comb_b) + gate bias preset
// ---------------------------------------------------------------------------
__global__ void k_comb(const int* __restrict__ tokens,
                       const float* __restrict__ emb,
                       const float* __restrict__ comb_W,
                       const float* __restrict__ comb_b,
                       const float* __restrict__ b_ih,
                       const float* __restrict__ b_hh) {
    if (threadIdx.x < 32) {
        int gi = blockIdx.x * 32 + threadIdx.x;
        g_gates[gi] = b_ih[gi] + b_hh[gi];
    }
    int warp = threadIdx.x >> 5, lane = threadIdx.x & 31;
    int row = blockIdx.x * 8 + warp;
    const float4* erow = (const float4*)(emb + (long)tokens[0] * H);
    const float4* arow = (const float4*)g_attn_applied;
    const float4* w    = (const float4*)(comb_W + (long)row * 2 * H);
    float4 wr[16];
    #pragma unroll
    for (int k = 0; k < 16; k++) wr[k] = __ldcs(w + lane + 32 * k);
    float acc = 0.f;
    #pragma unroll
    for (int k = 0; k < 16; k++) {
        int i = lane + 32 * k;
        float4 xv = (i < 256) ? erow[i] : arow[i - 256];
        acc += dot4(wr[k], xv);
    }
    acc = warp_sum(acc);
    if (lane == 0) g_x[row] = fmaxf(acc + comb_b[row], 0.f);
}

// ---------------------------------------------------------------------------
// k_gates: bulk-copy 2 x 16KB tiles (4 gate rows each) per block; partial dot
// atomicAdd into g_gates. Tiles 0..1023 = W_ih (vs x), 1024..2047 = W_hh (vs h).
// ---------------------------------------------------------------------------
__global__ void __launch_bounds__(128) k_gates(const float* __restrict__ W_ih,
                                               const float* __restrict__ W_hh,
                                               const float* __restrict__ h0) {
    __shared__ __align__(128) float4 buf[2][OT_TILE * 256];   // 32KB
    __shared__ float4 svx[256], svh[256];
    __shared__ uint64_t mbar[2];
    int tid = threadIdx.x, warp = tid >> 5, lane = tid & 31;
    uint64_t pol = mkpolicy();
    unsigned mb0 = smem_u32(&mbar[0]), mb1 = smem_u32(&mbar[1]);

    if (tid == 0) { mbar_init(mb0, 1); mbar_init(mb1, 1); }
    svx[tid]       = ((const float4*)g_x)[tid];
    svx[tid + 128] = ((const float4*)g_x)[tid + 128];
    svh[tid]       = ((const float4*)h0)[tid];
    svh[tid + 128] = ((const float4*)h0)[tid + 128];
    __syncthreads();

    int t0 = blockIdx.x * 2, t1 = t0 + 1;
    const float* s0 = (t0 < 1024) ? W_ih + (long)t0 * OT_TILE * H
                                  : W_hh + (long)(t0 - 1024) * OT_TILE * H;
    const float* s1 = (t1 < 1024) ? W_ih + (long)t1 * OT_TILE * H
                                  : W_hh + (long)(t1 - 1024) * OT_TILE * H;
    if (tid == 0) {
        mbar_expect(mb0, TILE_BYTES); bulk_cp(buf[0], s0, TILE_BYTES, mb0, pol);
        mbar_expect(mb1, TILE_BYTES); bulk_cp(buf[1], s1, TILE_BYTES, mb1, pol);
    }

    mbar_wait(mb0, 0);
    {
        const float4* vec = (t0 < 1024) ? svx : svh;
        float a = 0.f;
        #pragma unroll
        for (int k = 0; k < 8; k++) a += dot4(buf[0][warp * 256 + lane + 32 * k], vec[lane + 32 * k]);
        a = warp_sum(a);
        if (lane == 0) atomicAdd(&g_gates[(t0 * OT_TILE + warp) & 4095], a);
    }
    mbar_wait(mb1, 0);
    {
        const float4* vec = (t1 < 1024) ? svx : svh;
        float a = 0.f;
        #pragma unroll
        for (int k = 0; k < 8; k++) a += dot4(buf[1][warp * 256 + lane + 32 * k], vec[lane + 32 * k]);
        a = warp_sum(a);
        if (lane == 0) atomicAdd(&g_gates[(t1 * OT_TILE + warp) & 4095], a);
    }
}

// ---------------------------------------------------------------------------
// LSTM pointwise: gates -> c_new, h_new
// ---------------------------------------------------------------------------
__global__ void k_lstm_pw(const float* __restrict__ c0,
                          float* __restrict__ h_out, float* __restrict__ c_out) {
    int j = blockIdx.x * 256 + threadIdx.x;
    float gi = g_gates[j], gf = g_gates[H + j], gg = g_gates[2 * H + j], go = g_gates[3 * H + j];
    float ig = 1.f / (1.f + expf(-gi));
    float fg = 1.f / (1.f + expf(-gf));
    float gt = tanhf(gg);
    float og = 1.f / (1.f + expf(-go));
    float cn = fg * c0[j] + ig * gt;
    float hn = og * tanhf(cn);
    c_out[j] = cn;
    h_out[j] = hn;
    g_h[j]   = hn;
}

// ---------------------------------------------------------------------------
// output projection: persistent 592 blocks, 2-stage bulk-copy pipeline of
// 16KB tiles (4 rows), online logsumexp, fused last-block logZ.
// Tail row 50256 handled by block 0. Raw logits -> out.
// ---------------------------------------------------------------------------
__global__ void __launch_bounds__(128) k_out(const float* __restrict__ out_W,
                                             const float* __restrict__ out_b,
                                             float* __restrict__ out) {
    __shared__ __align__(128) float4 buf[2][OT_TILE * 256];   // 32KB
    __shared__ float4 sh4[256];
    __shared__ uint64_t mbar[2];
    __shared__ float  sm_m[4], sm_s[4];
    int tid = threadIdx.x, warp = tid >> 5, lane = tid & 31;
    uint64_t pol = mkpolicy();
    unsigned mb[2] = { smem_u32(&mbar[0]), smem_u32(&mbar[1]) };

    if (tid == 0) { mbar_init(mb[0], 1); mbar_init(mb[1], 1); }
    sh4[tid]       = ((const float4*)g_h)[tid];
    sh4[tid + 128] = ((const float4*)g_h)[tid + 128];
    __syncthreads();

    int nt = (OT_NTF - blockIdx.x + OT_GRID - 1) / OT_GRID;   // >= 21 for all blocks
    if (tid == 0) {
        mbar_expect(mb[0], TILE_BYTES);
        bulk_cp(buf[0], out_W + (long)blockIdx.x * OT_TILE * H, TILE_BYTES, mb[0], pol);
        mbar_expect(mb[1], TILE_BYTES);
        bulk_cp(buf[1], out_W + ((long)blockIdx.x + OT_GRID) * OT_TILE * H, TILE_BYTES, mb[1], pol);
    }

    float m = -INFINITY, ssum = 0.f;
    for (int i = 0; i < nt; i++) {
        int s = i & 1;
        mbar_wait(mb[s], (i >> 1) & 1);
        long row = ((long)blockIdx.x + (long)i * OT_GRID) * OT_TILE + warp;
        float a = 0.f;
        #pragma unroll
        for (int k = 0; k < 8; k++)
            a += dot4(buf[s][warp * 256 + lane + 32 * k], sh4[lane + 32 * k]);
        a = warp_sum(a);
        if (lane == 0) {
            float lg = a + out_b[row];
            out[row] = lg;
            if (lg > m) { ssum = ssum * expf(m - lg) + 1.f; m = lg; }
            else        { ssum += expf(lg - m); }
        }
        __syncthreads();   // all reads of buf[s] done before re-arm
        if (tid == 0 && i + 2 < nt) {
            mbar_expect(mb[s], TILE_BYTES);
            bulk_cp(buf[s], out_W + ((long)blockIdx.x + (long)(i + 2) * OT_GRID) * OT_TILE * H,
                    TILE_BYTES, mb[s], pol);
        }
    }

    // tail row 50256 (block 0, warp 0)
    if (blockIdx.x == 0 && warp == 0) {
        const float4* w = (const float4*)(out_W + (long)(OT_NTF * OT_TILE) * H);
        float a = 0.f;
        #pragma unroll
        for (int k = 0; k < 8; k++) a += dot4(__ldcs(w + lane + 32 * k), sh4[lane + 32 * k]);
        a = warp_sum(a);
        if (lane == 0) {
            int row = OT_NTF * OT_TILE;
            float lg = a + out_b[row];
            out[row] = lg;
            if (lg > m) { ssum = ssum * expf(m - lg) + 1.f; m = lg; }
            else        { ssum += expf(lg - m); }
        }
    }

    if (lane == 0) { sm_m[warp] = m; sm_s[warp] = ssum; }
    __syncthreads();
    __shared__ unsigned is_last;
    if (tid == 0) {
        float M = sm_m[0];
        #pragma unroll
        for (int k = 1; k < 4; k++) M = fmaxf(M, sm_m[k]);
        float S = 0.f;
        #pragma unroll
        for (int k = 0; k < 4; k++) S += sm_s[k] * expf(sm_m[k] - M);
        g_bmax[blockIdx.x] = M;
        g_bsum[blockIdx.x] = S;
        __threadfence();
        is_last = (atomicAdd(&g_ctr_out, 1u) == OT_GRID - 1);
    }
    __syncthreads();
    if (!is_last) return;

    __threadfence();
    float mm = -INFINITY;
    for (int k = tid; k < OT_GRID; k += 128) mm = fmaxf(mm, g_bmax[k]);
    __shared__ float red[4];
    mm = warp_max(mm);
    if (lane == 0) red[warp] = mm;
    __syncthreads();
    if (tid == 0) {
        float z = fmaxf(fmaxf(red[0], red[1]), fmaxf(red[2], red[3]));
        red[0] = z;
    }
    __syncthreads();
    float M = red[0];
    __syncthreads();
    float S = 0.f;
    for (int k = tid; k < OT_GRID; k += 128) S += g_bsum[k] * expf(g_bmax[k] - M);
    S = warp_sum(S);
    if (lane == 0) red[warp] = S;
    __syncthreads();
    if (tid == 0) {
        g_logZ = M + logf(red[0] + red[1] + red[2] + red[3]);
        g_ctr_out = 0;
    }
}

__global__ void k_final(float* __restrict__ out) {
    int v = blockIdx.x * blockDim.x + threadIdx.x;
    if (v >= V) return;
    out[v] -= g_logZ;
}

extern "C" void kernel_launch(void* const* d_in, const int* in_sizes, int n_in,
                              void* d_out, int out_size) {
    const int*   tokens = (const int*)  d_in[0];
    const float* h0     = (const float*)d_in[1];
    const float* c0     = (const float*)d_in[2];
    const float* enc    = (const float*)d_in[3];
    const float* emb    = (const float*)d_in[4];
    const float* attn_W = (const float*)d_in[5];
    const float* attn_b = (const float*)d_in[6];
    const float* comb_W = (const float*)d_in[7];
    const float* comb_b = (const float*)d_in[8];
    const float* W_ih   = (const float*)d_in[9];
    const float* W_hh   = (const float*)d_in[10];
    const float* b_ih   = (const float*)d_in[11];
    const float* b_hh   = (const float*)d_in[12];
    const float* out_W  = (const float*)d_in[13];
    const float* out_b  = (const float*)d_in[14];

    float* out    = (float*)d_out;          // [V] log-probs
    float* h_out  = out + V;                // [H]
    float* c_out  = out + V + H;            // [H]
    float* aw_out = out + V + 2 * H;        // [L]

    k_attn        <<<L, 256>>>(tokens, emb, h0, attn_W, attn_b, aw_out);
    k_attn_applied<<<H / 32, 256>>>(enc);
    k_comb        <<<H / 8, 256>>>(tokens, emb, comb_W, comb_b, b_ih, b_hh);
    k_gates       <<<GT_TILES / 2, 128>>>(W_ih, W_hh, h0);
    k_lstm_pw     <<<H / 256, 256>>>(c0, h_out, c_out);
    k_out         <<<OT_GRID, 128>>>(out_W, out_b, out);
    k_final       <<<(V + 511) / 512, 512>>>(out);
}